// round 16
// baseline (speedup 1.0000x reference)
#include <cuda_runtime.h>
#include <cuda_fp16.h>
#include <stdint.h>
#include <math.h>

#define B_  16
#define N_  1024
#define D_  768
#define H_  12
#define HD_ 64
#define M_  (B_ * N_)            // 16384
#define SCALE2_ 0.05205928822087216f   // (1/sqrt(768)) * log2(e)

// ---- device scratch (no allocation in kernel_launch) ----
__device__ __half g_xt[M_ * D_];            // X in fp16
__device__ __half g_wqkvt[3 * D_ * D_];     // W_{q,k,v}^T  [n=2304][k=768] fp16
__device__ __half g_wot[D_ * D_];           // W_o^T        [n][k] fp16
__device__ float  g_bqkv[3 * D_];
__device__ __half g_q[B_ * H_ * N_ * HD_];  // [b][h][n][d] (scale*log2e folded)
__device__ __half g_k[B_ * H_ * N_ * HD_];  // [b][h][n][d]
__device__ __half g_v[B_ * H_ * HD_ * N_];  // [b][h][d][n] (transposed)
__device__ __half g_ao[M_ * D_];            // attn out

// ---------------------------------------------------------------------------
__device__ __forceinline__ uint32_t packh2(float lo, float hi) {
    uint32_t r;
    asm("cvt.rn.f16x2.f32 %0, %1, %2;" : "=r"(r) : "f"(hi), "f"(lo));
    return r;   // low 16 bits = lo, high = hi
}
__device__ __forceinline__ uint32_t ex2h2(uint32_t a) {
    uint32_t r;
    asm("ex2.approx.f16x2 %0, %1;" : "=r"(r) : "r"(a));
    return r;
}
__device__ __forceinline__ uint32_t hadd2(uint32_t a, uint32_t b) {
    uint32_t r;
    asm("add.rn.f16x2 %0, %1, %2;" : "=r"(r) : "r"(a), "r"(b));
    return r;
}
__device__ __forceinline__ void mma16(float c[4], const uint32_t a[4],
                                      uint32_t b0, uint32_t b1) {
    asm volatile(
        "mma.sync.aligned.m16n8k16.row.col.f32.f16.f16.f32 "
        "{%0,%1,%2,%3}, {%4,%5,%6,%7}, {%8,%9}, {%0,%1,%2,%3};"
        : "+f"(c[0]), "+f"(c[1]), "+f"(c[2]), "+f"(c[3])
        : "r"(a[0]), "r"(a[1]), "r"(a[2]), "r"(a[3]), "r"(b0), "r"(b1));
}
__device__ __forceinline__ uint32_t smaddr(const void* p) {
    return (uint32_t)__cvta_generic_to_shared(p);
}
__device__ __forceinline__ void ldsm4(uint32_t r[4], const void* p) {
    uint32_t a = smaddr(p);
    asm volatile("ldmatrix.sync.aligned.m8n8.x4.shared.b16 {%0,%1,%2,%3}, [%4];"
                 : "=r"(r[0]), "=r"(r[1]), "=r"(r[2]), "=r"(r[3]) : "r"(a));
}
__device__ __forceinline__ void cp16(void* sp, const void* gp) {
    asm volatile("cp.async.cg.shared.global [%0], [%1], 16;"
                 :: "r"(smaddr(sp)), "l"(gp));
}
#define CP_COMMIT asm volatile("cp.async.commit_group;")
#define CP_WAIT0  asm volatile("cp.async.wait_group 0;")
#define CP_WAIT1  asm volatile("cp.async.wait_group 1;")
#define ONESH2 0x3C003C00u

// ---------------------------------------------------------------------------
// prep kernels (one-time)
// ---------------------------------------------------------------------------
__global__ void prep_x(const float* __restrict__ X, __half* __restrict__ Xt) {
    size_t i = ((size_t)blockIdx.x * 256 + threadIdx.x) * 4;
    float4 v = *(const float4*)(X + i);
    uint2 u = make_uint2(packh2(v.x, v.y), packh2(v.z, v.w));
    *(uint2*)(Xt + i) = u;
}

// z = 0..3: transpose+convert Wq/Wk/Wv/Wo; z = 4 (block 0,0 only): pack biases
__global__ void prep_w(const float* __restrict__ Wq, const float* __restrict__ Wk,
                       const float* __restrict__ Wv, const float* __restrict__ Wo,
                       const float* __restrict__ bq, const float* __restrict__ bk,
                       const float* __restrict__ bv,
                       __half* __restrict__ Wqkvt, __half* __restrict__ Wot,
                       float* __restrict__ bqkv) {
    const int z = blockIdx.z;
    if (z == 4) {
        if (blockIdx.x == 0 && blockIdx.y == 0) {
            const int t = threadIdx.y * 32 + threadIdx.x;   // 0..255
            for (int i = t; i < D_; i += 256) {
                bqkv[i]          = bq[i];
                bqkv[D_ + i]     = bk[i];
                bqkv[2 * D_ + i] = bv[i];
            }
        }
        return;
    }
    __shared__ float t[32][33];
    const float* src = (z == 0) ? Wq : (z == 1) ? Wk : (z == 2) ? Wv : Wo;
    __half* dst = (z < 3) ? (Wqkvt + (size_t)z * D_ * D_) : Wot;
    const int x0 = blockIdx.x * 32;   // n
    const int y0 = blockIdx.y * 32;   // k
    const int tx = threadIdx.x, ty = threadIdx.y;
#pragma unroll
    for (int r = 0; r < 4; r++)
        t[ty + 8 * r][tx] = src[(size_t)(y0 + ty + 8 * r) * D_ + x0 + tx];
    __syncthreads();
#pragma unroll
    for (int r = 0; r < 4; r++)
        dst[(size_t)(x0 + ty + 8 * r) * D_ + y0 + tx] = __float2half_rn(t[tx][ty + 8 * r]);
}

// ---------------------------------------------------------------------------
// fp16 HMMA GEMM (R11 config — pareto-optimal for this chip/shape):
// CTA 128x128, k-stage 64, single-sync double buffer, 4 warps (2x2),
// warp tile 64x64, m16n8k16, 3 CTAs/SM.
// ---------------------------------------------------------------------------
#define HS 72                               // padded stride, halfs (144 B)
#define GEMM_STAGE_H (128 * HS)             // per A or B stage, halfs
#define GEMM_SMEM (4 * GEMM_STAGE_H * 2)    // 2 stages x (A+B) x 2B = 73728
#define NKT_ (D_ / 64)                      // 12 k-iters

template <int MODE>
__global__ __launch_bounds__(128)
void gemm3(const __half* __restrict__ A, const __half* __restrict__ Bt,
           const float* __restrict__ bias, float* __restrict__ outF,
           __half* __restrict__ oq, __half* __restrict__ ok,
           __half* __restrict__ ov)
{
    extern __shared__ __half sh[];

    const int tid  = threadIdx.x;
    const int lane = tid & 31;
    const int wid  = tid >> 5;
    const int wm   = (wid >> 1) * 64;
    const int wn   = (wid & 1) * 64;
    const int m0   = blockIdx.y * 128;
    const int n0   = blockIdx.x * 128;

    const int lr = tid >> 3;             // 0..15
    const int lc = (tid & 7) * 8;        // 0..56 (halfs)
    const __half* Ap = A  + (size_t)(m0 + lr) * D_ + lc;
    const __half* Bp = Bt + (size_t)(n0 + lr) * D_ + lc;

    float acc[4][8][4];
#pragma unroll
    for (int i = 0; i < 4; i++)
#pragma unroll
        for (int j = 0; j < 8; j++)
#pragma unroll
            for (int r = 0; r < 4; r++) acc[i][j][r] = 0.f;

    auto fill = [&](int s, int t) {
        __half* as = sh + s * 2 * GEMM_STAGE_H;
        __half* bs = as + GEMM_STAGE_H;
#pragma unroll
        for (int p = 0; p < 8; p++) {
            const int row = lr + 16 * p;
            cp16(&as[row * HS + lc], Ap + (size_t)16 * p * D_ + t * 64);
            cp16(&bs[row * HS + lc], Bp + (size_t)16 * p * D_ + t * 64);
        }
    };

    fill(0, 0); CP_COMMIT;

    int buf = 0;
    for (int it = 0; it < NKT_; it++) {
        CP_WAIT0;
        __syncthreads();
        if (it + 1 < NKT_) {
            fill(buf ^ 1, it + 1);
            CP_COMMIT;
        }

        const __half* as = sh + buf * 2 * GEMM_STAGE_H;
        const __half* bs = as + GEMM_STAGE_H;
#pragma unroll
        for (int kk = 0; kk < 4; kk++) {
            const int kb = kk * 16;
            uint32_t af[4][4];
#pragma unroll
            for (int i = 0; i < 4; i++)
                ldsm4(af[i], &as[(wm + i * 16 + (lane & 15)) * HS + kb + 8 * (lane >> 4)]);
            uint32_t bf[4][4];
#pragma unroll
            for (int jj = 0; jj < 4; jj++)
                ldsm4(bf[jj], &bs[(wn + jj * 16 + ((lane >> 4) << 3) + (lane & 7)) * HS
                                  + kb + 8 * ((lane >> 3) & 1)]);
#pragma unroll
            for (int i = 0; i < 4; i++)
#pragma unroll
                for (int jj = 0; jj < 4; jj++) {
                    mma16(acc[i][2 * jj],     af[i], bf[jj][0], bf[jj][1]);
                    mma16(acc[i][2 * jj + 1], af[i], bf[jj][2], bf[jj][3]);
                }
        }
        buf ^= 1;
    }

    // epilogue (direct stores)
    const int mrow0 = m0 + wm + (lane >> 2);
    const int col0  = n0 + wn + 2 * (lane & 3);
#pragma unroll
    for (int i = 0; i < 4; i++) {
#pragma unroll
        for (int j = 0; j < 8; j++) {
            const int row = mrow0 + i * 16;
            const int col = col0 + j * 8;
            const float2 bv = *(const float2*)(bias + col);
            float c0 = acc[i][j][0] + bv.x, c1 = acc[i][j][1] + bv.y;
            float c2 = acc[i][j][2] + bv.x, c3 = acc[i][j][3] + bv.y;
            if (MODE == 0) {
                *(float2*)(outF + (size_t)row * D_ + col)       = make_float2(c0, c1);
                *(float2*)(outF + (size_t)(row + 8) * D_ + col) = make_float2(c2, c3);
            } else {
                const int which = n0 / D_;        // uniform per CTA
                const int ncol  = col - which * D_;
                const int h = ncol >> 6, d = ncol & 63;
                const int b = row >> 10, r = row & 1023;
                if (which == 0) {
                    __half* base = oq + ((((size_t)b * H_ + h) * N_) + r) * HD_ + d;
                    *(uint32_t*)base             = packh2(c0 * SCALE2_, c1 * SCALE2_);
                    *(uint32_t*)(base + 8 * HD_) = packh2(c2 * SCALE2_, c3 * SCALE2_);
                } else if (which == 1) {
                    __half* base = ok + ((((size_t)b * H_ + h) * N_) + r) * HD_ + d;
                    *(uint32_t*)base             = packh2(c0, c1);
                    *(uint32_t*)(base + 8 * HD_) = packh2(c2, c3);
                } else {
                    __half* base = ov + (((size_t)b * H_ + h) * HD_ + d) * N_ + r;
                    base[0]      = __float2half_rn(c0);
                    base[N_]     = __float2half_rn(c1);
                    base[8]      = __float2half_rn(c2);
                    base[N_ + 8] = __float2half_rn(c3);
                }
            }
        }
    }
}

// ---------------------------------------------------------------------------
// fp16 flash attention: no-max softmax, hoisted Q fragments, triple-buffered
// K/V. Row-sums via ONE ones-mma per (i, iter) on HADD2-presummed P
// fragments (saves 6 tensor ops/iter vs per-chunk ones-mma).
// CTA = 128 q rows, 128 threads (4 warps x 32 q rows), 3 CTAs/SM.
// ---------------------------------------------------------------------------
#define ATTN_SMEM ((128 + 3 * 64 + 3 * 64) * HS * 2)   // 73728 B
#define NT_ (N_ / 64)                                  // 16 key tiles

__global__ __launch_bounds__(128)
void attn7(const __half* __restrict__ Q, const __half* __restrict__ K,
           const __half* __restrict__ V, __half* __restrict__ O)
{
    extern __shared__ __half sh[];
    __half* Qs = sh;                        // [128][HS]
    __half* Kb = sh + 128 * HS;             // [3][64][HS]
    __half* Vb = sh + (128 + 192) * HS;     // [3][64][HS]  ([d][key])

    const int tid  = threadIdx.x;
    const int lane = tid & 31;
    const int wid  = tid >> 5;
    const int b    = blockIdx.z;
    const int h    = blockIdx.y;
    const int q0   = blockIdx.x * 128;

    const __half* Qg = Q + (((size_t)b * H_ + h) * N_ + q0) * HD_;
    const __half* Kg = K + (((size_t)b * H_ + h) * N_) * HD_;
    const __half* Vg = V + (((size_t)b * H_ + h) * HD_) * N_;

    const int fr = tid >> 3;              // 0..15
    const int fc = (tid & 7) * 8;         // 0..56

    auto fill_kv = [&](int s, int t) {
        __half* kd = Kb + s * 64 * HS;
        __half* vd = Vb + s * 64 * HS;
        const __half* kg = Kg + (size_t)t * 64 * HD_;
        const __half* vg = Vg + (size_t)t * 64;
#pragma unroll
        for (int p = 0; p < 4; p++) {
            const int row = fr + 16 * p;
            cp16(&kd[row * HS + fc], kg + (size_t)row * HD_ + fc);
            cp16(&vd[row * HS + fc], vg + (size_t)row * N_ + fc);
        }
    };

    // prologue: group0 = Q + K/V tile 0; group1 = K/V tile 1
#pragma unroll
    for (int p = 0; p < 8; p++) {
        const int row = fr + 16 * p;
        cp16(&Qs[row * HS + fc], Qg + (size_t)row * HD_ + fc);
    }
    fill_kv(0, 0);
    CP_COMMIT;
    fill_kv(1, 1);
    CP_COMMIT;

    float oa[2][8][4];
    float lacc[2][4];
#pragma unroll
    for (int i = 0; i < 2; i++) {
#pragma unroll
        for (int r = 0; r < 4; r++) lacc[i][r] = 0.f;
#pragma unroll
        for (int nt = 0; nt < 8; nt++)
#pragma unroll
            for (int r = 0; r < 4; r++) oa[i][nt][r] = 0.f;
    }

    const int qbase = wid * 32;

    CP_WAIT1;            // group0 (Q + K/V tile 0) arrived; tile 1 in flight
    __syncthreads();

    // ---- hoist Q fragments (loop-invariant) ----
    uint32_t qa[4][2][4];   // [kk][i][frag]
#pragma unroll
    for (int kk = 0; kk < 4; kk++)
#pragma unroll
        for (int i = 0; i < 2; i++)
            ldsm4(qa[kk][i], &Qs[(qbase + i * 16 + (lane & 15)) * HS
                                 + kk * 16 + 8 * (lane >> 4)]);

    int s = 0;   // stage of tile t
    for (int t = 0; t < NT_; t++) {
        if (t > 0) {
            if (t < NT_ - 1) { CP_WAIT1; } else { CP_WAIT0; }
            __syncthreads();   // tile t ready; stage (t+2)%3's old readers done
        }
        if (t + 2 < NT_) {
            fill_kv((s + 2) % 3, t + 2);
            CP_COMMIT;
        }

        const __half* Kt = Kb + s * 64 * HS;
        const __half* Vt = Vb + s * 64 * HS;

        // ---- S = Q K^T (32 q x 64 keys per warp) ----
        float sa[2][8][4];
#pragma unroll
        for (int i = 0; i < 2; i++)
#pragma unroll
            for (int nt = 0; nt < 8; nt++)
#pragma unroll
                for (int r = 0; r < 4; r++) sa[i][nt][r] = 0.f;

#pragma unroll
        for (int kk = 0; kk < 4; kk++) {
            const int kb = kk * 16;
            uint32_t kf[4][4];
#pragma unroll
            for (int jj = 0; jj < 4; jj++)
                ldsm4(kf[jj], &Kt[(jj * 16 + ((lane >> 4) << 3) + (lane & 7)) * HS
                                  + kb + 8 * ((lane >> 3) & 1)]);
#pragma unroll
            for (int i = 0; i < 2; i++)
#pragma unroll
                for (int jj = 0; jj < 4; jj++) {
                    mma16(sa[i][2 * jj],     qa[kk][i], kf[jj][0], kf[jj][1]);
                    mma16(sa[i][2 * jj + 1], qa[kk][i], kf[jj][2], kf[jj][3]);
                }
        }

        // ---- P = exp2(S) packed fp16; O += P @ V; row sums presummed ----
        uint32_t psum[2][4];
#pragma unroll
        for (int i = 0; i < 2; i++)
#pragma unroll
            for (int r = 0; r < 4; r++) psum[i][r] = 0u;

#pragma unroll
        for (int kk = 0; kk < 4; kk++) {     // keys 16kk..16kk+15
            const int kb = kk * 16;
            uint32_t pa[2][4];
#pragma unroll
            for (int i = 0; i < 2; i++) {
                pa[i][0] = ex2h2(packh2(sa[i][2 * kk][0],     sa[i][2 * kk][1]));
                pa[i][1] = ex2h2(packh2(sa[i][2 * kk][2],     sa[i][2 * kk][3]));
                pa[i][2] = ex2h2(packh2(sa[i][2 * kk + 1][0], sa[i][2 * kk + 1][1]));
                pa[i][3] = ex2h2(packh2(sa[i][2 * kk + 1][2], sa[i][2 * kk + 1][3]));
#pragma unroll
                for (int r = 0; r < 4; r++)
                    psum[i][r] = hadd2(psum[i][r], pa[i][r]);
            }
            uint32_t vf[4][4];
#pragma unroll
            for (int jj = 0; jj < 4; jj++)
                ldsm4(vf[jj], &Vt[(jj * 16 + ((lane >> 4) << 3) + (lane & 7)) * HS
                                  + kb + 8 * ((lane >> 3) & 1)]);
#pragma unroll
            for (int i = 0; i < 2; i++)
#pragma unroll
                for (int jj = 0; jj < 4; jj++) {
                    mma16(oa[i][2 * jj],     pa[i], vf[jj][0], vf[jj][1]);
                    mma16(oa[i][2 * jj + 1], pa[i], vf[jj][2], vf[jj][3]);
                }
        }
        // one ones-mma per i: lacc += (sum_kk P_kk) @ ones
#pragma unroll
        for (int i = 0; i < 2; i++)
            mma16(lacc[i], psum[i], ONESH2, ONESH2);

        s = (s + 1) % 3;
    }

    // ---- normalize + store fp16 into g_ao [M][768] ----
#pragma unroll
    for (int i = 0; i < 2; i++) {
        const float inv0 = 1.f / lacc[i][0];   // rows qbase+i*16+(lane>>2)
        const float inv1 = 1.f / lacc[i][2];   // +8
        const int row = b * N_ + q0 + qbase + i * 16 + (lane >> 2);
        __half* Op = O + (size_t)row * D_ + h * HD_;
#pragma unroll
        for (int nt = 0; nt < 8; nt++) {
            const int cc = nt * 8 + 2 * (lane & 3);
            *(uint32_t*)(Op + cc) =
                packh2(oa[i][nt][0] * inv0, oa[i][nt][1] * inv0);
            *(uint32_t*)(Op + (size_t)8 * D_ + cc) =
                packh2(oa[i][nt][2] * inv1, oa[i][nt][3] * inv1);
        }
    }
}

// ---------------------------------------------------------------------------
extern "C" void kernel_launch(void* const* d_in, const int* in_sizes, int n_in,
                              void* d_out, int out_size)
{
    const float* X  = (const float*)d_in[0];
    const float* Wq = (const float*)d_in[1];
    const float* bq = (const float*)d_in[2];
    const float* Wk = (const float*)d_in[3];
    const float* bk = (const float*)d_in[4];
    const float* Wv = (const float*)d_in[5];
    const float* bv = (const float*)d_in[6];
    const float* Wo = (const float*)d_in[7];
    const float* bo = (const float*)d_in[8];
    float* out = (float*)d_out;

    __half *xt, *wqkvt, *wot, *qp, *kp, *vp, *aop;
    float* bqkv;
    cudaGetSymbolAddress((void**)&xt,    g_xt);
    cudaGetSymbolAddress((void**)&wqkvt, g_wqkvt);
    cudaGetSymbolAddress((void**)&wot,   g_wot);
    cudaGetSymbolAddress((void**)&bqkv,  g_bqkv);
    cudaGetSymbolAddress((void**)&qp,    g_q);
    cudaGetSymbolAddress((void**)&kp,    g_k);
    cudaGetSymbolAddress((void**)&vp,    g_v);
    cudaGetSymbolAddress((void**)&aop,   g_ao);

    cudaFuncSetAttribute(gemm3<1>, cudaFuncAttributeMaxDynamicSharedMemorySize, GEMM_SMEM);
    cudaFuncSetAttribute(gemm3<0>, cudaFuncAttributeMaxDynamicSharedMemorySize, GEMM_SMEM);
    cudaFuncSetAttribute(attn7,    cudaFuncAttributeMaxDynamicSharedMemorySize, ATTN_SMEM);

    prep_x<<<M_ * D_ / 1024, 256>>>(X, xt);
    prep_w<<<dim3(24, 24, 5), dim3(32, 8)>>>(Wq, Wk, Wv, Wo, bq, bk, bv,
                                             wqkvt, wot, bqkv);

    gemm3<1><<<dim3(3 * D_ / 128, M_ / 128), 128, GEMM_SMEM>>>(
        xt, wqkvt, bqkv, nullptr, qp, kp, vp);

    attn7<<<dim3(N_ / 128, H_, B_), 128, ATTN_SMEM>>>(qp, kp, vp, aop);

    gemm3<0><<<dim3(D_ / 128, M_ / 128), 128, GEMM_SMEM>>>(
        aop, wot, bo, out, nullptr, nullptr, nullptr);
}

// round 17
// speedup vs baseline: 1.0287x; 1.0287x over previous
#include <cuda_runtime.h>
#include <cuda_fp16.h>
#include <stdint.h>
#include <math.h>

#define B_  16
#define N_  1024
#define D_  768
#define H_  12
#define HD_ 64
#define M_  (B_ * N_)            // 16384
#define SCALE2_ 0.05205928822087216f   // (1/sqrt(768)) * log2(e)

// ---- device scratch (no allocation in kernel_launch) ----
__device__ __half g_xt[M_ * D_];            // X in fp16
__device__ __half g_wqkvt[3 * D_ * D_];     // W_{q,k,v}^T  [n=2304][k=768] fp16
__device__ __half g_wot[D_ * D_];           // W_o^T        [n][k] fp16
__device__ float  g_bqkv[3 * D_];
__device__ __half g_q[B_ * H_ * N_ * HD_];  // [b][h][n][d] (scale*log2e folded)
__device__ __half g_k[B_ * H_ * N_ * HD_];  // [b][h][n][d]
__device__ __half g_v[B_ * H_ * HD_ * N_];  // [b][h][d][n] (transposed)
__device__ __half g_ao[M_ * D_];            // attn out

// ---------------------------------------------------------------------------
__device__ __forceinline__ uint32_t packh2(float lo, float hi) {
    uint32_t r;
    asm("cvt.rn.f16x2.f32 %0, %1, %2;" : "=r"(r) : "f"(hi), "f"(lo));
    return r;   // low 16 bits = lo, high = hi
}
__device__ __forceinline__ uint32_t ex2h2(uint32_t a) {
    uint32_t r;
    asm("ex2.approx.f16x2 %0, %1;" : "=r"(r) : "r"(a));
    return r;
}
__device__ __forceinline__ void mma16(float c[4], const uint32_t a[4],
                                      uint32_t b0, uint32_t b1) {
    asm volatile(
        "mma.sync.aligned.m16n8k16.row.col.f32.f16.f16.f32 "
        "{%0,%1,%2,%3}, {%4,%5,%6,%7}, {%8,%9}, {%0,%1,%2,%3};"
        : "+f"(c[0]), "+f"(c[1]), "+f"(c[2]), "+f"(c[3])
        : "r"(a[0]), "r"(a[1]), "r"(a[2]), "r"(a[3]), "r"(b0), "r"(b1));
}
__device__ __forceinline__ uint32_t smaddr(const void* p) {
    return (uint32_t)__cvta_generic_to_shared(p);
}
__device__ __forceinline__ void ldsm4(uint32_t r[4], const void* p) {
    uint32_t a = smaddr(p);
    asm volatile("ldmatrix.sync.aligned.m8n8.x4.shared.b16 {%0,%1,%2,%3}, [%4];"
                 : "=r"(r[0]), "=r"(r[1]), "=r"(r[2]), "=r"(r[3]) : "r"(a));
}
__device__ __forceinline__ void cp16(void* sp, const void* gp) {
    asm volatile("cp.async.cg.shared.global [%0], [%1], 16;"
                 :: "r"(smaddr(sp)), "l"(gp));
}
#define CP_COMMIT asm volatile("cp.async.commit_group;")
#define CP_WAIT0  asm volatile("cp.async.wait_group 0;")
#define CP_WAIT1  asm volatile("cp.async.wait_group 1;")
#define ONESH2 0x3C003C00u

// ---------------------------------------------------------------------------
// prep kernels (one-time)
// ---------------------------------------------------------------------------
__global__ void prep_x(const float* __restrict__ X, __half* __restrict__ Xt) {
    size_t i = ((size_t)blockIdx.x * 256 + threadIdx.x) * 4;
    float4 v = *(const float4*)(X + i);
    uint2 u = make_uint2(packh2(v.x, v.y), packh2(v.z, v.w));
    *(uint2*)(Xt + i) = u;
}

// z = 0..3: transpose+convert Wq/Wk/Wv/Wo; z = 4 (block 0,0 only): pack biases
__global__ void prep_w(const float* __restrict__ Wq, const float* __restrict__ Wk,
                       const float* __restrict__ Wv, const float* __restrict__ Wo,
                       const float* __restrict__ bq, const float* __restrict__ bk,
                       const float* __restrict__ bv,
                       __half* __restrict__ Wqkvt, __half* __restrict__ Wot,
                       float* __restrict__ bqkv) {
    const int z = blockIdx.z;
    if (z == 4) {
        if (blockIdx.x == 0 && blockIdx.y == 0) {
            const int t = threadIdx.y * 32 + threadIdx.x;   // 0..255
            for (int i = t; i < D_; i += 256) {
                bqkv[i]          = bq[i];
                bqkv[D_ + i]     = bk[i];
                bqkv[2 * D_ + i] = bv[i];
            }
        }
        return;
    }
    __shared__ float t[32][33];
    const float* src = (z == 0) ? Wq : (z == 1) ? Wk : (z == 2) ? Wv : Wo;
    __half* dst = (z < 3) ? (Wqkvt + (size_t)z * D_ * D_) : Wot;
    const int x0 = blockIdx.x * 32;   // n
    const int y0 = blockIdx.y * 32;   // k
    const int tx = threadIdx.x, ty = threadIdx.y;
#pragma unroll
    for (int r = 0; r < 4; r++)
        t[ty + 8 * r][tx] = src[(size_t)(y0 + ty + 8 * r) * D_ + x0 + tx];
    __syncthreads();
#pragma unroll
    for (int r = 0; r < 4; r++)
        dst[(size_t)(x0 + ty + 8 * r) * D_ + y0 + tx] = __float2half_rn(t[tx][ty + 8 * r]);
}

// ---------------------------------------------------------------------------
// fp16 HMMA GEMM (R11 config — pareto-optimal for this chip/shape):
// CTA 128x128, k-stage 64, single-sync double buffer, 4 warps (2x2),
// warp tile 64x64, m16n8k16, 3 CTAs/SM.
// ---------------------------------------------------------------------------
#define HS 72                               // padded stride, halfs (144 B)
#define GEMM_STAGE_H (128 * HS)             // per A or B stage, halfs
#define GEMM_SMEM (4 * GEMM_STAGE_H * 2)    // 2 stages x (A+B) x 2B = 73728
#define NKT_ (D_ / 64)                      // 12 k-iters

template <int MODE>
__global__ __launch_bounds__(128)
void gemm3(const __half* __restrict__ A, const __half* __restrict__ Bt,
           const float* __restrict__ bias, float* __restrict__ outF,
           __half* __restrict__ oq, __half* __restrict__ ok,
           __half* __restrict__ ov)
{
    extern __shared__ __half sh[];

    const int tid  = threadIdx.x;
    const int lane = tid & 31;
    const int wid  = tid >> 5;
    const int wm   = (wid >> 1) * 64;
    const int wn   = (wid & 1) * 64;
    const int m0   = blockIdx.y * 128;
    const int n0   = blockIdx.x * 128;

    const int lr = tid >> 3;             // 0..15
    const int lc = (tid & 7) * 8;        // 0..56 (halfs)
    const __half* Ap = A  + (size_t)(m0 + lr) * D_ + lc;
    const __half* Bp = Bt + (size_t)(n0 + lr) * D_ + lc;

    float acc[4][8][4];
#pragma unroll
    for (int i = 0; i < 4; i++)
#pragma unroll
        for (int j = 0; j < 8; j++)
#pragma unroll
            for (int r = 0; r < 4; r++) acc[i][j][r] = 0.f;

    auto fill = [&](int s, int t) {
        __half* as = sh + s * 2 * GEMM_STAGE_H;
        __half* bs = as + GEMM_STAGE_H;
#pragma unroll
        for (int p = 0; p < 8; p++) {
            const int row = lr + 16 * p;
            cp16(&as[row * HS + lc], Ap + (size_t)16 * p * D_ + t * 64);
            cp16(&bs[row * HS + lc], Bp + (size_t)16 * p * D_ + t * 64);
        }
    };

    fill(0, 0); CP_COMMIT;

    int buf = 0;
    for (int it = 0; it < NKT_; it++) {
        CP_WAIT0;
        __syncthreads();
        if (it + 1 < NKT_) {
            fill(buf ^ 1, it + 1);
            CP_COMMIT;
        }

        const __half* as = sh + buf * 2 * GEMM_STAGE_H;
        const __half* bs = as + GEMM_STAGE_H;
#pragma unroll
        for (int kk = 0; kk < 4; kk++) {
            const int kb = kk * 16;
            uint32_t af[4][4];
#pragma unroll
            for (int i = 0; i < 4; i++)
                ldsm4(af[i], &as[(wm + i * 16 + (lane & 15)) * HS + kb + 8 * (lane >> 4)]);
            uint32_t bf[4][4];
#pragma unroll
            for (int jj = 0; jj < 4; jj++)
                ldsm4(bf[jj], &bs[(wn + jj * 16 + ((lane >> 4) << 3) + (lane & 7)) * HS
                                  + kb + 8 * ((lane >> 3) & 1)]);
#pragma unroll
            for (int i = 0; i < 4; i++)
#pragma unroll
                for (int jj = 0; jj < 4; jj++) {
                    mma16(acc[i][2 * jj],     af[i], bf[jj][0], bf[jj][1]);
                    mma16(acc[i][2 * jj + 1], af[i], bf[jj][2], bf[jj][3]);
                }
        }
        buf ^= 1;
    }

    // epilogue (direct stores)
    const int mrow0 = m0 + wm + (lane >> 2);
    const int col0  = n0 + wn + 2 * (lane & 3);
#pragma unroll
    for (int i = 0; i < 4; i++) {
#pragma unroll
        for (int j = 0; j < 8; j++) {
            const int row = mrow0 + i * 16;
            const int col = col0 + j * 8;
            const float2 bv = *(const float2*)(bias + col);
            float c0 = acc[i][j][0] + bv.x, c1 = acc[i][j][1] + bv.y;
            float c2 = acc[i][j][2] + bv.x, c3 = acc[i][j][3] + bv.y;
            if (MODE == 0) {
                *(float2*)(outF + (size_t)row * D_ + col)       = make_float2(c0, c1);
                *(float2*)(outF + (size_t)(row + 8) * D_ + col) = make_float2(c2, c3);
            } else {
                const int which = n0 / D_;        // uniform per CTA
                const int ncol  = col - which * D_;
                const int h = ncol >> 6, d = ncol & 63;
                const int b = row >> 10, r = row & 1023;
                if (which == 0) {
                    __half* base = oq + ((((size_t)b * H_ + h) * N_) + r) * HD_ + d;
                    *(uint32_t*)base             = packh2(c0 * SCALE2_, c1 * SCALE2_);
                    *(uint32_t*)(base + 8 * HD_) = packh2(c2 * SCALE2_, c3 * SCALE2_);
                } else if (which == 1) {
                    __half* base = ok + ((((size_t)b * H_ + h) * N_) + r) * HD_ + d;
                    *(uint32_t*)base             = packh2(c0, c1);
                    *(uint32_t*)(base + 8 * HD_) = packh2(c2, c3);
                } else {
                    __half* base = ov + (((size_t)b * H_ + h) * HD_ + d) * N_ + r;
                    base[0]      = __float2half_rn(c0);
                    base[N_]     = __float2half_rn(c1);
                    base[8]      = __float2half_rn(c2);
                    base[N_ + 8] = __float2half_rn(c3);
                }
            }
        }
    }
}

// ---------------------------------------------------------------------------
// fp16 flash attention (R15 attn7 — 168 regs, 3 CTAs/SM): no-max softmax,
// hoisted Q fragments, triple-buffered K/V (prefetch distance 2),
// row-sums via per-chunk ones-mma (register-neutral).
// CTA = 128 q rows, 128 threads (4 warps x 32 q rows).
// ---------------------------------------------------------------------------
#define ATTN_SMEM ((128 + 3 * 64 + 3 * 64) * HS * 2)   // 73728 B
#define NT_ (N_ / 64)                                  // 16 key tiles

__global__ __launch_bounds__(128)
void attn7(const __half* __restrict__ Q, const __half* __restrict__ K,
           const __half* __restrict__ V, __half* __restrict__ O)
{
    extern __shared__ __half sh[];
    __half* Qs = sh;                        // [128][HS]
    __half* Kb = sh + 128 * HS;             // [3][64][HS]
    __half* Vb = sh + (128 + 192) * HS;     // [3][64][HS]  ([d][key])

    const int tid  = threadIdx.x;
    const int lane = tid & 31;
    const int wid  = tid >> 5;
    const int b    = blockIdx.z;
    const int h    = blockIdx.y;
    const int q0   = blockIdx.x * 128;

    const __half* Qg = Q + (((size_t)b * H_ + h) * N_ + q0) * HD_;
    const __half* Kg = K + (((size_t)b * H_ + h) * N_) * HD_;
    const __half* Vg = V + (((size_t)b * H_ + h) * HD_) * N_;

    const int fr = tid >> 3;              // 0..15
    const int fc = (tid & 7) * 8;         // 0..56

    auto fill_kv = [&](int s, int t) {
        __half* kd = Kb + s * 64 * HS;
        __half* vd = Vb + s * 64 * HS;
        const __half* kg = Kg + (size_t)t * 64 * HD_;
        const __half* vg = Vg + (size_t)t * 64;
#pragma unroll
        for (int p = 0; p < 4; p++) {
            const int row = fr + 16 * p;
            cp16(&kd[row * HS + fc], kg + (size_t)row * HD_ + fc);
            cp16(&vd[row * HS + fc], vg + (size_t)row * N_ + fc);
        }
    };

    // prologue: group0 = Q + K/V tile 0; group1 = K/V tile 1
#pragma unroll
    for (int p = 0; p < 8; p++) {
        const int row = fr + 16 * p;
        cp16(&Qs[row * HS + fc], Qg + (size_t)row * HD_ + fc);
    }
    fill_kv(0, 0);
    CP_COMMIT;
    fill_kv(1, 1);
    CP_COMMIT;

    float oa[2][8][4];
    float lacc[2][4];
#pragma unroll
    for (int i = 0; i < 2; i++) {
#pragma unroll
        for (int r = 0; r < 4; r++) lacc[i][r] = 0.f;
#pragma unroll
        for (int nt = 0; nt < 8; nt++)
#pragma unroll
            for (int r = 0; r < 4; r++) oa[i][nt][r] = 0.f;
    }

    const int qbase = wid * 32;

    CP_WAIT1;            // group0 (Q + K/V tile 0) arrived; tile 1 in flight
    __syncthreads();

    // ---- hoist Q fragments (loop-invariant) ----
    uint32_t qa[4][2][4];   // [kk][i][frag]
#pragma unroll
    for (int kk = 0; kk < 4; kk++)
#pragma unroll
        for (int i = 0; i < 2; i++)
            ldsm4(qa[kk][i], &Qs[(qbase + i * 16 + (lane & 15)) * HS
                                 + kk * 16 + 8 * (lane >> 4)]);

    int s = 0;   // stage of tile t
    for (int t = 0; t < NT_; t++) {
        if (t > 0) {
            if (t < NT_ - 1) { CP_WAIT1; } else { CP_WAIT0; }
            __syncthreads();   // tile t ready; stage (t+2)%3's old readers done
        }
        if (t + 2 < NT_) {
            fill_kv((s + 2) % 3, t + 2);
            CP_COMMIT;
        }

        const __half* Kt = Kb + s * 64 * HS;
        const __half* Vt = Vb + s * 64 * HS;

        // ---- S = Q K^T (32 q x 64 keys per warp) ----
        float sa[2][8][4];
#pragma unroll
        for (int i = 0; i < 2; i++)
#pragma unroll
            for (int nt = 0; nt < 8; nt++)
#pragma unroll
                for (int r = 0; r < 4; r++) sa[i][nt][r] = 0.f;

#pragma unroll
        for (int kk = 0; kk < 4; kk++) {
            const int kb = kk * 16;
            uint32_t kf[4][4];
#pragma unroll
            for (int jj = 0; jj < 4; jj++)
                ldsm4(kf[jj], &Kt[(jj * 16 + ((lane >> 4) << 3) + (lane & 7)) * HS
                                  + kb + 8 * ((lane >> 3) & 1)]);
#pragma unroll
            for (int i = 0; i < 2; i++)
#pragma unroll
                for (int jj = 0; jj < 4; jj++) {
                    mma16(sa[i][2 * jj],     qa[kk][i], kf[jj][0], kf[jj][1]);
                    mma16(sa[i][2 * jj + 1], qa[kk][i], kf[jj][2], kf[jj][3]);
                }
        }

        // ---- P = exp2(S) packed fp16; O += P @ V; l += P @ ones ----
#pragma unroll
        for (int kk = 0; kk < 4; kk++) {     // keys 16kk..16kk+15
            const int kb = kk * 16;
            uint32_t pa[2][4];
#pragma unroll
            for (int i = 0; i < 2; i++) {
                pa[i][0] = ex2h2(packh2(sa[i][2 * kk][0],     sa[i][2 * kk][1]));
                pa[i][1] = ex2h2(packh2(sa[i][2 * kk][2],     sa[i][2 * kk][3]));
                pa[i][2] = ex2h2(packh2(sa[i][2 * kk + 1][0], sa[i][2 * kk + 1][1]));
                pa[i][3] = ex2h2(packh2(sa[i][2 * kk + 1][2], sa[i][2 * kk + 1][3]));
            }
            uint32_t vf[4][4];
#pragma unroll
            for (int jj = 0; jj < 4; jj++)
                ldsm4(vf[jj], &Vt[(jj * 16 + ((lane >> 4) << 3) + (lane & 7)) * HS
                                  + kb + 8 * ((lane >> 3) & 1)]);
#pragma unroll
            for (int i = 0; i < 2; i++) {
#pragma unroll
                for (int jj = 0; jj < 4; jj++) {
                    mma16(oa[i][2 * jj],     pa[i], vf[jj][0], vf[jj][1]);
                    mma16(oa[i][2 * jj + 1], pa[i], vf[jj][2], vf[jj][3]);
                }
                mma16(lacc[i], pa[i], ONESH2, ONESH2);   // row sums
            }
        }

        s = (s + 1) % 3;
    }

    // ---- normalize + store fp16 into g_ao [M][768] ----
#pragma unroll
    for (int i = 0; i < 2; i++) {
        const float inv0 = 1.f / lacc[i][0];   // rows qbase+i*16+(lane>>2)
        const float inv1 = 1.f / lacc[i][2];   // +8
        const int row = b * N_ + q0 + qbase + i * 16 + (lane >> 2);
        __half* Op = O + (size_t)row * D_ + h * HD_;
#pragma unroll
        for (int nt = 0; nt < 8; nt++) {
            const int cc = nt * 8 + 2 * (lane & 3);
            *(uint32_t*)(Op + cc) =
                packh2(oa[i][nt][0] * inv0, oa[i][nt][1] * inv0);
            *(uint32_t*)(Op + (size_t)8 * D_ + cc) =
                packh2(oa[i][nt][2] * inv1, oa[i][nt][3] * inv1);
        }
    }
}

// ---------------------------------------------------------------------------
extern "C" void kernel_launch(void* const* d_in, const int* in_sizes, int n_in,
                              void* d_out, int out_size)
{
    const float* X  = (const float*)d_in[0];
    const float* Wq = (const float*)d_in[1];
    const float* bq = (const float*)d_in[2];
    const float* Wk = (const float*)d_in[3];
    const float* bk = (const float*)d_in[4];
    const float* Wv = (const float*)d_in[5];
    const float* bv = (const float*)d_in[6];
    const float* Wo = (const float*)d_in[7];
    const float* bo = (const float*)d_in[8];
    float* out = (float*)d_out;

    __half *xt, *wqkvt, *wot, *qp, *kp, *vp, *aop;
    float* bqkv;
    cudaGetSymbolAddress((void**)&xt,    g_xt);
    cudaGetSymbolAddress((void**)&wqkvt, g_wqkvt);
    cudaGetSymbolAddress((void**)&wot,   g_wot);
    cudaGetSymbolAddress((void**)&bqkv,  g_bqkv);
    cudaGetSymbolAddress((void**)&qp,    g_q);
    cudaGetSymbolAddress((void**)&kp,    g_k);
    cudaGetSymbolAddress((void**)&vp,    g_v);
    cudaGetSymbolAddress((void**)&aop,   g_ao);

    cudaFuncSetAttribute(gemm3<1>, cudaFuncAttributeMaxDynamicSharedMemorySize, GEMM_SMEM);
    cudaFuncSetAttribute(gemm3<0>, cudaFuncAttributeMaxDynamicSharedMemorySize, GEMM_SMEM);
    cudaFuncSetAttribute(attn7,    cudaFuncAttributeMaxDynamicSharedMemorySize, ATTN_SMEM);

    prep_x<<<M_ * D_ / 1024, 256>>>(X, xt);
    prep_w<<<dim3(24, 24, 5), dim3(32, 8)>>>(Wq, Wk, Wv, Wo, bq, bk, bv,
                                             wqkvt, wot, bqkv);

    gemm3<1><<<dim3(3 * D_ / 128, M_ / 128), 128, GEMM_SMEM>>>(
        xt, wqkvt, bqkv, nullptr, qp, kp, vp);

    attn7<<<dim3(N_ / 128, H_, B_), 128, ATTN_SMEM>>>(qp, kp, vp, aop);

    gemm3<0><<<dim3(D_ / 128, M_ / 128), 128, GEMM_SMEM>>>(
        aop, wot, bo, out, nullptr, nullptr, nullptr);
}